// round 1
// baseline (speedup 1.0000x reference)
#include <cuda_runtime.h>
#include <stdint.h>
#include <math.h>

// Problem constants (fixed shapes for PryIO_38560216383637)
#define Nn 8
#define Tt 256
#define Bb 4
#define Dd 512
#define Vv 32000
#define Mm (Nn*Tt*Bb)          // 8192 rows
#define VSPLITS 10
#define VCHUNK (Vv/VSPLITS)    // 3200

// GEMM tile config
#define BM 128
#define BN 128
#define BK 16

// Scratch (no allocations allowed -> __device__ globals)
__device__ float g_pval[Mm*VSPLITS];
__device__ int   g_pidx[Mm*VSPLITS];
__device__ int   g_maxidx[Mm];
__device__ float g_scores[Mm];

// ---------------------------------------------------------------------------
// Kernel 1: fused fp32 GEMM (A[M,K] * W[V,K]^T) + argmax-over-V epilogue.
// Grid: (M/BM, VSPLITS). Each CTA owns BM rows and a V-range of VCHUNK cols,
// keeps running (best,idx) per row, writes one partial per (row, split).
// ---------------------------------------------------------------------------
__global__ void __launch_bounds__(256, 2)
argmax_gemm_kernel(const float* __restrict__ A, const float* __restrict__ W)
{
    __shared__ float As[BK][BM];
    __shared__ float Bs[BK][BN];

    const int tid = threadIdx.x;
    const int tx  = tid & 15;          // column group (8 cols)
    const int ty  = tid >> 4;          // row group (8 rows)
    const int m0  = blockIdx.x * BM;
    const int v0  = blockIdx.y * VCHUNK;

    float best[8];
    int   bidx[8];
#pragma unroll
    for (int i = 0; i < 8; ++i) { best[i] = -INFINITY; bidx[i] = 0; }

    for (int vt = v0; vt < v0 + VCHUNK; vt += BN) {
        float acc[8][8];
#pragma unroll
        for (int i = 0; i < 8; ++i) {
#pragma unroll
            for (int j = 0; j < 8; ++j) acc[i][j] = 0.f;
        }

        for (int kt = 0; kt < Dd; kt += BK) {
            // Stage A tile (BMxBK) and B tile (BNxBK) into smem, transposed to [k][row]
#pragma unroll
            for (int q = 0; q < 2; ++q) {
                int s   = tid * 2 + q;      // 0..511 float4 slots
                int row = s >> 2;           // 0..127
                int kc  = (s & 3) << 2;     // 0,4,8,12
                float4 va = *(const float4*)(A + (size_t)(m0 + row) * Dd + kt + kc);
                As[kc+0][row] = va.x; As[kc+1][row] = va.y;
                As[kc+2][row] = va.z; As[kc+3][row] = va.w;
                float4 vb = *(const float4*)(W + (size_t)(vt + row) * Dd + kt + kc);
                Bs[kc+0][row] = vb.x; Bs[kc+1][row] = vb.y;
                Bs[kc+2][row] = vb.z; Bs[kc+3][row] = vb.w;
            }
            __syncthreads();

#pragma unroll
            for (int kk = 0; kk < BK; ++kk) {
                float a[8], b[8];
                *(float4*)(a)     = *(const float4*)(&As[kk][ty*8]);
                *(float4*)(a + 4) = *(const float4*)(&As[kk][ty*8 + 4]);
                *(float4*)(b)     = *(const float4*)(&Bs[kk][tx*8]);
                *(float4*)(b + 4) = *(const float4*)(&Bs[kk][tx*8 + 4]);
#pragma unroll
                for (int i = 0; i < 8; ++i) {
#pragma unroll
                    for (int j = 0; j < 8; ++j)
                        acc[i][j] = fmaf(a[i], b[j], acc[i][j]);
                }
            }
            __syncthreads();
        }

        // Argmax epilogue for this V-tile (ascending v keeps first-max tie rule)
#pragma unroll
        for (int i = 0; i < 8; ++i) {
#pragma unroll
            for (int j = 0; j < 8; ++j) {
                int v = vt + tx * 8 + j;
                if (acc[i][j] > best[i]) { best[i] = acc[i][j]; bidx[i] = v; }
            }
        }
    }

    // Reduce across the 16 tx lanes (contiguous lanes within a warp, width 16)
#pragma unroll
    for (int i = 0; i < 8; ++i) {
        float v  = best[i];
        int   id = bidx[i];
#pragma unroll
        for (int off = 8; off > 0; off >>= 1) {
            float ov = __shfl_down_sync(0xffffffffu, v, off, 16);
            int   oi = __shfl_down_sync(0xffffffffu, id, off, 16);
            if (ov > v || (ov == v && oi < id)) { v = ov; id = oi; }
        }
        if (tx == 0) {
            int r = m0 + ty * 8 + i;
            g_pval[(size_t)r * VSPLITS + blockIdx.y] = v;
            g_pidx[(size_t)r * VSPLITS + blockIdx.y] = id;
        }
    }
}

// ---------------------------------------------------------------------------
// Kernel 2: reduce per-split partials -> final argmax index per row.
// Splits scanned in ascending v order; strict > keeps first occurrence.
// ---------------------------------------------------------------------------
__global__ void reduce_argmax_kernel()
{
    int r = blockIdx.x * blockDim.x + threadIdx.x;
    if (r >= Mm) return;
    float bv = g_pval[(size_t)r * VSPLITS];
    int   bi = g_pidx[(size_t)r * VSPLITS];
#pragma unroll
    for (int s = 1; s < VSPLITS; ++s) {
        float v = g_pval[(size_t)r * VSPLITS + s];
        int   i = g_pidx[(size_t)r * VSPLITS + s];
        if (v > bv) { bv = v; bi = i; }
    }
    g_maxidx[r] = bi;
}

// ---------------------------------------------------------------------------
// Kernel 3: scores[r] = sqrt(D) * dot(outputs[n,t,:], W[maxidx[r],:])
// One warp per row.
// ---------------------------------------------------------------------------
__global__ void scores_kernel(const float* __restrict__ outputs,
                              const float* __restrict__ W)
{
    int gthread = blockIdx.x * blockDim.x + threadIdx.x;
    int warp = gthread >> 5;
    int lane = threadIdx.x & 31;
    if (warp >= Mm) return;

    int n  = warp >> 10;          // / (T*B)
    int tb = warp & 1023;
    int t  = tb >> 2;

    const float* orow = outputs + ((size_t)(n * Tt + t)) * Dd;
    const float* wrow = W + (size_t)g_maxidx[warp] * Dd;

    float s = 0.f;
#pragma unroll
    for (int k = 0; k < Dd / 32; ++k) {
        int d = lane + k * 32;
        s = fmaf(orow[d], wrow[d], s);
    }
#pragma unroll
    for (int off = 16; off > 0; off >>= 1)
        s += __shfl_xor_sync(0xffffffffu, s, off);

    if (lane == 0)
        g_scores[warp] = s * 22.62741699796952f;   // float32(sqrt(512))
}

// ---------------------------------------------------------------------------
// JAX threefry2x32 (20 rounds, 5 key injections) — must be bit-exact.
// ---------------------------------------------------------------------------
__device__ __forceinline__ uint32_t rotl32(uint32_t x, int d)
{
    return (x << d) | (x >> (32 - d));
}

__device__ __forceinline__ void threefry2x32(uint32_t k0, uint32_t k1,
                                             uint32_t x0, uint32_t x1,
                                             uint32_t& o0, uint32_t& o1)
{
    uint32_t k2 = k0 ^ k1 ^ 0x1BD11BDAu;
    x0 += k0; x1 += k1;
    // set 1: rot {13,15,26,6}
    x0 += x1; x1 = rotl32(x1, 13); x1 ^= x0;
    x0 += x1; x1 = rotl32(x1, 15); x1 ^= x0;
    x0 += x1; x1 = rotl32(x1, 26); x1 ^= x0;
    x0 += x1; x1 = rotl32(x1,  6); x1 ^= x0;
    x0 += k1; x1 += k2 + 1u;
    // set 2: rot {17,29,16,24}
    x0 += x1; x1 = rotl32(x1, 17); x1 ^= x0;
    x0 += x1; x1 = rotl32(x1, 29); x1 ^= x0;
    x0 += x1; x1 = rotl32(x1, 16); x1 ^= x0;
    x0 += x1; x1 = rotl32(x1, 24); x1 ^= x0;
    x0 += k2; x1 += k0 + 2u;
    // set 3
    x0 += x1; x1 = rotl32(x1, 13); x1 ^= x0;
    x0 += x1; x1 = rotl32(x1, 15); x1 ^= x0;
    x0 += x1; x1 = rotl32(x1, 26); x1 ^= x0;
    x0 += x1; x1 = rotl32(x1,  6); x1 ^= x0;
    x0 += k0; x1 += k1 + 3u;
    // set 4
    x0 += x1; x1 = rotl32(x1, 17); x1 ^= x0;
    x0 += x1; x1 = rotl32(x1, 29); x1 ^= x0;
    x0 += x1; x1 = rotl32(x1, 16); x1 ^= x0;
    x0 += x1; x1 = rotl32(x1, 24); x1 ^= x0;
    x0 += k1; x1 += k2 + 4u;
    // set 5
    x0 += x1; x1 = rotl32(x1, 13); x1 ^= x0;
    x0 += x1; x1 = rotl32(x1, 15); x1 ^= x0;
    x0 += x1; x1 = rotl32(x1, 26); x1 ^= x0;
    x0 += x1; x1 = rotl32(x1,  6); x1 ^= x0;
    x0 += k2; x1 += k0 + 5u;
    o0 = x0; o1 = x1;
}

// ---------------------------------------------------------------------------
// Kernel 4: precompute uniforms (partitionable threefry, JAX>=0.5 default),
// then run the sequential accept/reject scan (8 independent lanes) and emit
// the mask. Single block.
//
// fold_in(key(42), t) = threefry((0,42), (0,t))   [mode-independent]
// uniform(key_t, (8,)) partitionable: per i, (h0,h1)=threefry(key_t,(0,i));
//   bits = h0 ^ h1; u = bitcast((bits>>9)|0x3f800000) - 1.
// ---------------------------------------------------------------------------
__global__ void scan_kernel(float* __restrict__ out)
{
    __shared__ float s_sc[Mm];        // 32 KB scores
    __shared__ float s_u[Tt][8];      // 8 KB uniforms

    int tid = threadIdx.x;            // 256 threads

    // Zero output (poisoned by harness)
    for (int i = tid; i < Mm; i += 256) out[i] = 0.f;
    // Stage scores
    for (int i = tid; i < Mm; i += 256) s_sc[i] = g_scores[i];

    // One thread per t: fold_in + 8 uniforms
    {
        int t = tid;   // 0..255 == Tt
        uint32_t kt0, kt1;
        threefry2x32(0u, 42u, 0u, (uint32_t)t, kt0, kt1);
#pragma unroll
        for (int n = 0; n < 8; ++n) {
            uint32_t o0, o1;
            threefry2x32(kt0, kt1, 0u, (uint32_t)n, o0, o1);
            uint32_t bits = o0 ^ o1;
            s_u[t][n] = __uint_as_float((bits >> 9) | 0x3f800000u) - 1.0f;
        }
    }
    __syncthreads();

    if (tid < 8) {
        int n = tid;
        int x = 0, y = 0;
        const float* scn = s_sc + n * 1024;
        float* outn = out + n * 1024;
        for (int t = 0; t < Tt; ++t) {
            int idx0 = x * Bb + y;
            outn[idx0] = 1.0f;
            float z = (scn[idx0] - scn[t * 4]) / 10.0f;
            float prob = (float)(1.0 / (1.0 + exp(-(double)z)));
            int accept = (s_u[t][n] < prob) ? 1 : 0;
            if (y + accept >= Bb) accept = 0;       // block full -> reject
            y = (y + accept) * accept;              // accept: y+1, else 0
            x = accept ? x : (t + 1);               // accept: stay, else t+1
        }
    }
}

// ---------------------------------------------------------------------------
extern "C" void kernel_launch(void* const* d_in, const int* in_sizes, int n_in,
                              void* d_out, int out_size)
{
    (void)in_sizes; (void)n_in; (void)out_size;
    const float* outputs       = (const float*)d_in[0];   // [N,T,D]
    const float* block_outputs = (const float*)d_in[1];   // [N,T,B,D]
    const float* W             = (const float*)d_in[2];   // [V,D]
    float* out = (float*)d_out;                            // [N,T,B]

    argmax_gemm_kernel<<<dim3(Mm / BM, VSPLITS), 256>>>(block_outputs, W);
    reduce_argmax_kernel<<<Mm / 256, 256>>>();
    scores_kernel<<<(Mm * 32) / 256, 256>>>(outputs, W);
    scan_kernel<<<1, 256>>>(out);
}

// round 3
// speedup vs baseline: 7.1082x; 7.1082x over previous
#include <cuda_runtime.h>
#include <cuda_bf16.h>
#include <stdint.h>
#include <math.h>

// Problem constants
#define Nn 8
#define Tt 256
#define Bb 4
#define Dd 512
#define Vv 32000
#define Mm (Nn*Tt*Bb)          // 8192 rows

// GEMM tiling
#define BM 128
#define BN 128
#define BK 32
#define NUM_K (Dd/BK)          // 16
#define NTILES (Vv/BN)         // 250
#define SA_STRIDE 40           // 32 + 8 pad elems -> 80B rows (conflict-free)

// ---------------------------------------------------------------------------
// Device scratch (no allocations allowed)
// ---------------------------------------------------------------------------
__device__ __align__(16) __nv_bfloat16 g_Abf[Mm*Dd];      // 8 MB
__device__ __align__(16) __nv_bfloat16 g_Wbf[Vv*Dd];      // 32 MB
__device__ float g_c1v[Mm*NTILES];
__device__ int   g_c1i[Mm*NTILES];
__device__ float g_c2v[Mm*NTILES];
__device__ int   g_c2i[Mm*NTILES];
__device__ int   g_maxidx[Mm];
__device__ float g_scores[Mm];

// ---------------------------------------------------------------------------
__device__ __forceinline__ uint32_t smem_u32(const void* p) {
    uint32_t a;
    asm("{ .reg .u64 t; cvta.to.shared.u64 t, %1; cvt.u32.u64 %0, t; }" : "=r"(a) : "l"(p));
    return a;
}
__device__ __forceinline__ void ldsm_x4(uint32_t& a0, uint32_t& a1, uint32_t& a2,
                                        uint32_t& a3, uint32_t addr) {
    asm volatile("ldmatrix.sync.aligned.m8n8.x4.shared.b16 {%0,%1,%2,%3}, [%4];"
                 : "=r"(a0), "=r"(a1), "=r"(a2), "=r"(a3) : "r"(addr));
}
__device__ __forceinline__ void ldsm_x2(uint32_t& b0, uint32_t& b1, uint32_t addr) {
    asm volatile("ldmatrix.sync.aligned.m8n8.x2.shared.b16 {%0,%1}, [%2];"
                 : "=r"(b0), "=r"(b1) : "r"(addr));
}
__device__ __forceinline__ void mma_bf16(float* c, uint32_t a0, uint32_t a1,
                                         uint32_t a2, uint32_t a3,
                                         uint32_t b0, uint32_t b1) {
    asm volatile("mma.sync.aligned.m16n8k16.row.col.f32.bf16.bf16.f32 "
                 "{%0,%1,%2,%3}, {%4,%5,%6,%7}, {%8,%9}, {%0,%1,%2,%3};"
                 : "+f"(c[0]), "+f"(c[1]), "+f"(c[2]), "+f"(c[3])
                 : "r"(a0), "r"(a1), "r"(a2), "r"(a3), "r"(b0), "r"(b1));
}

__device__ __forceinline__ void top2_insert(float& v1, int& i1, float& v2, int& i2,
                                            float v, int idx) {
    if (v > v1) { v2 = v1; i2 = i1; v1 = v; i1 = idx; }
    else if (v > v2) { v2 = v; i2 = idx; }
}
__device__ __forceinline__ void top2_merge(float& v1, int& i1, float& v2, int& i2,
                                           float ov1, int oi1, float ov2, int oi2) {
    if (ov1 > v1) {
        if (v1 > ov2) { v2 = v1; i2 = i1; } else { v2 = ov2; i2 = oi2; }
        v1 = ov1; i1 = oi1;
    } else {
        if (ov1 > v2) { v2 = ov1; i2 = oi1; }
    }
}

// ---------------------------------------------------------------------------
// Kernel 0: fp32 -> bf16 conversion for A (block_outputs) and W
// ---------------------------------------------------------------------------
#define A4 (Mm*Dd/4)
#define W4 (Vv*Dd/4)
__global__ void convert_kernel(const float* __restrict__ A, const float* __restrict__ W)
{
    int i = blockIdx.x * blockDim.x + threadIdx.x;
    if (i < A4) {
        float4 v = ((const float4*)A)[i];
        __nv_bfloat162 p0 = __floats2bfloat162_rn(v.x, v.y);
        __nv_bfloat162 p1 = __floats2bfloat162_rn(v.z, v.w);
        *(uint2*)(g_Abf + (size_t)i * 4) = make_uint2(*(uint32_t*)&p0, *(uint32_t*)&p1);
    } else if (i < A4 + W4) {
        int j = i - A4;
        float4 v = ((const float4*)W)[j];
        __nv_bfloat162 p0 = __floats2bfloat162_rn(v.x, v.y);
        __nv_bfloat162 p1 = __floats2bfloat162_rn(v.z, v.w);
        *(uint2*)(g_Wbf + (size_t)j * 4) = make_uint2(*(uint32_t*)&p0, *(uint32_t*)&p1);
    }
}

// ---------------------------------------------------------------------------
// Kernel 1: bf16 mma.sync GEMM (HMMA) + top-2-per-(row,vtile) epilogue.
// Grid (Mm/BM=64, NTILES=250), 256 threads = 8 warps (2 M x 4 N), warp 64x32.
// ---------------------------------------------------------------------------
__global__ void __launch_bounds__(256, 2)
argmax_gemm_kernel()
{
    __shared__ __align__(16) __nv_bfloat16 sA[2][BM * SA_STRIDE];
    __shared__ __align__(16) __nv_bfloat16 sB[2][BN * SA_STRIDE];

    const int tid = threadIdx.x;
    const int lane = tid & 31, wid = tid >> 5;
    const int wm = wid >> 2, wn = wid & 3;      // warp coords: 2 x 4
    const int m0 = blockIdx.x * BM;
    const int v0 = blockIdx.y * BN;

    // Global load mapping: 512 uint4 slots per tile; thread does slot tid, tid+256
    const int lr = tid >> 2;                    // 0..63
    const int lc = (tid & 3) * 8;               // elem col 0,8,16,24
    const __nv_bfloat16* gA = g_Abf + (size_t)(m0 + lr) * Dd + lc;
    const __nv_bfloat16* gW = g_Wbf + (size_t)(v0 + lr) * Dd + lc;
    const int smoff0 = lr * SA_STRIDE + lc;             // rows lr, lr+64
    const int smoff1 = (lr + 64) * SA_STRIDE + lc;

    // ldmatrix per-thread address components
    const int aRow = lane & 15;
    const int aKof = (lane >> 4) * 8;
    const int l2 = lane & 15;
    const int bRow = l2 & 7;
    const int bKof = ((l2 >> 3) & 1) * 8;

    uint32_t sa_base[2], sb_base[2];
    sa_base[0] = smem_u32(sA[0]); sa_base[1] = smem_u32(sA[1]);
    sb_base[0] = smem_u32(sB[0]); sb_base[1] = smem_u32(sB[1]);

    float acc[4][4][4];
#pragma unroll
    for (int a = 0; a < 4; ++a)
#pragma unroll
        for (int b = 0; b < 4; ++b)
#pragma unroll
            for (int c = 0; c < 4; ++c) acc[a][b][c] = 0.f;

    uint4 ra0, ra1, rb0, rb1;

    // Prologue: tile 0
    ra0 = *(const uint4*)(gA);
    ra1 = *(const uint4*)(gA + (size_t)64 * Dd);
    rb0 = *(const uint4*)(gW);
    rb1 = *(const uint4*)(gW + (size_t)64 * Dd);
    *(uint4*)(sA[0] + smoff0) = ra0; *(uint4*)(sA[0] + smoff1) = ra1;
    *(uint4*)(sB[0] + smoff0) = rb0; *(uint4*)(sB[0] + smoff1) = rb1;
    __syncthreads();

    for (int kt = 0; kt < NUM_K; ++kt) {
        const int buf = kt & 1;
        if (kt + 1 < NUM_K) {
            int g = (kt + 1) * BK;
            ra0 = *(const uint4*)(gA + g);
            ra1 = *(const uint4*)(gA + g + (size_t)64 * Dd);
            rb0 = *(const uint4*)(gW + g);
            rb1 = *(const uint4*)(gW + g + (size_t)64 * Dd);
        }

#pragma unroll
        for (int s = 0; s < 2; ++s) {
            uint32_t bf[4][2];
#pragma unroll
            for (int nf = 0; nf < 4; ++nf) {
                uint32_t addr = sb_base[buf] +
                    2u * (uint32_t)((wn * 32 + nf * 8 + bRow) * SA_STRIDE + s * 16 + bKof);
                ldsm_x2(bf[nf][0], bf[nf][1], addr);
            }
#pragma unroll
            for (int mf = 0; mf < 4; ++mf) {
                uint32_t a0, a1, a2, a3;
                uint32_t addr = sa_base[buf] +
                    2u * (uint32_t)((wm * 64 + mf * 16 + aRow) * SA_STRIDE + s * 16 + aKof);
                ldsm_x4(a0, a1, a2, a3, addr);
#pragma unroll
                for (int nf = 0; nf < 4; ++nf)
                    mma_bf16(acc[mf][nf], a0, a1, a2, a3, bf[nf][0], bf[nf][1]);
            }
        }

        if (kt + 1 < NUM_K) {
            const int nb = buf ^ 1;
            *(uint4*)(sA[nb] + smoff0) = ra0; *(uint4*)(sA[nb] + smoff1) = ra1;
            *(uint4*)(sB[nb] + smoff0) = rb0; *(uint4*)(sB[nb] + smoff1) = rb1;
        }
        __syncthreads();
    }

    // Epilogue: per-row top-2 over this CTA's 128 V-columns.
    float4* s_red = (float4*)sA;    // [128 rows][4 warps-in-N], 8KB (reuse)
    const int colBase = v0 + wn * 32 + (lane & 3) * 2;

#pragma unroll
    for (int mf = 0; mf < 4; ++mf) {
#pragma unroll
        for (int half = 0; half < 2; ++half) {   // half 0: rows r; half 1: rows r+8
            float v1 = -INFINITY, v2 = -INFINITY;
            int i1 = 0, i2 = 0;
#pragma unroll
            for (int nf = 0; nf < 4; ++nf) {
#pragma unroll
                for (int c = 0; c < 2; ++c) {
                    float v = acc[mf][nf][half * 2 + c];
                    top2_insert(v1, i1, v2, i2, v, colBase + nf * 8 + c);
                }
            }
#pragma unroll
            for (int off = 2; off >= 1; off >>= 1) {
                float ov1 = __shfl_down_sync(0xffffffffu, v1, off, 4);
                int   oi1 = __shfl_down_sync(0xffffffffu, i1, off, 4);
                float ov2 = __shfl_down_sync(0xffffffffu, v2, off, 4);
                int   oi2 = __shfl_down_sync(0xffffffffu, i2, off, 4);
                top2_merge(v1, i1, v2, i2, ov1, oi1, ov2, oi2);
            }
            if ((lane & 3) == 0) {
                int row = wm * 64 + mf * 16 + (lane >> 2) + half * 8;
                s_red[row * 4 + wn] =
                    make_float4(v1, __int_as_float(i1), v2, __int_as_float(i2));
            }
        }
    }
    __syncthreads();

    if (tid < BM) {
        float v1, v2; int i1, i2;
        float4 t = s_red[tid * 4 + 0];
        v1 = t.x; i1 = __float_as_int(t.y); v2 = t.z; i2 = __float_as_int(t.w);
#pragma unroll
        for (int w = 1; w < 4; ++w) {
            float4 u = s_red[tid * 4 + w];
            top2_merge(v1, i1, v2, i2, u.x, __float_as_int(u.y), u.z, __float_as_int(u.w));
        }
        size_t o = (size_t)(m0 + tid) * NTILES + blockIdx.y;
        g_c1v[o] = v1; g_c1i[o] = i1;
        g_c2v[o] = v2; g_c2i[o] = i2;
    }
}

// ---------------------------------------------------------------------------
// Kernel 2: per-row candidate merge + exact fp32 rescore -> g_maxidx
// 8 warps / block, one warp per row.
// ---------------------------------------------------------------------------
#define MAXCAND 96
#define NC (2*NTILES)
__global__ void finalize_kernel(const float* __restrict__ A, const float* __restrict__ W)
{
    const int wip = threadIdx.x >> 5;
    const int lane = threadIdx.x & 31;
    const int row = blockIdx.x * 8 + wip;
    __shared__ int s_cnt[8];
    __shared__ int s_idx[8][MAXCAND];

    // Approx max over all candidates
    float mx = -INFINITY;
    for (int i = lane; i < NC; i += 32) {
        float v = (i < NTILES) ? g_c1v[(size_t)row * NTILES + i]
                               : g_c2v[(size_t)row * NTILES + (i - NTILES)];
        mx = fmaxf(mx, v);
    }
#pragma unroll
    for (int off = 16; off > 0; off >>= 1)
        mx = fmaxf(mx, __shfl_xor_sync(0xffffffffu, mx, off));

    const float thr = mx - 0.04f;
    if (lane == 0) s_cnt[wip] = 0;
    __syncwarp();
    for (int i = lane; i < NC; i += 32) {
        float v; int id;
        if (i < NTILES) { v = g_c1v[(size_t)row * NTILES + i]; id = g_c1i[(size_t)row * NTILES + i]; }
        else { v = g_c2v[(size_t)row * NTILES + (i - NTILES)]; id = g_c2i[(size_t)row * NTILES + (i - NTILES)]; }
        if (v >= thr) {
            int p = atomicAdd(&s_cnt[wip], 1);
            if (p < MAXCAND) s_idx[wip][p] = id;
        }
    }
    __syncwarp();
    int cnt = min(s_cnt[wip], MAXCAND);
    if (lane == 0) {     // ascending index order -> deterministic first-max tie rule
        for (int a = 1; a < cnt; ++a) {
            int key = s_idx[wip][a]; int b = a - 1;
            while (b >= 0 && s_idx[wip][b] > key) { s_idx[wip][b + 1] = s_idx[wip][b]; --b; }
            s_idx[wip][b + 1] = key;
        }
    }
    __syncwarp();

    const float* arow = A + (size_t)row * Dd;
    float bestv = -INFINITY; int besti = 0;
    for (int c = 0; c < cnt; ++c) {
        const float* wrow = W + (size_t)s_idx[wip][c] * Dd;
        float s = 0.f;
#pragma unroll
        for (int k = 0; k < Dd / 32; ++k)
            s = fmaf(arow[lane + k * 32], wrow[lane + k * 32], s);
#pragma unroll
        for (int off = 16; off > 0; off >>= 1)
            s += __shfl_xor_sync(0xffffffffu, s, off);
        if (s > bestv) { bestv = s; besti = s_idx[wip][c]; }
    }
    if (lane == 0) g_maxidx[row] = besti;
}

// ---------------------------------------------------------------------------
// Kernel 3: scores[r] = sqrt(D) * dot(outputs[n,t,:], W[maxidx[r],:]) (fp32)
// ---------------------------------------------------------------------------
__global__ void scores_kernel(const float* __restrict__ outputs,
                              const float* __restrict__ W)
{
    int gthread = blockIdx.x * blockDim.x + threadIdx.x;
    int warp = gthread >> 5;
    int lane = threadIdx.x & 31;
    if (warp >= Mm) return;

    int n = warp >> 10;
    int t = (warp & 1023) >> 2;

    const float* orow = outputs + ((size_t)(n * Tt + t)) * Dd;
    const float* wrow = W + (size_t)g_maxidx[warp] * Dd;

    float s = 0.f;
#pragma unroll
    for (int k = 0; k < Dd / 32; ++k)
        s = fmaf(orow[lane + k * 32], wrow[lane + k * 32], s);
#pragma unroll
    for (int off = 16; off > 0; off >>= 1)
        s += __shfl_xor_sync(0xffffffffu, s, off);

    if (lane == 0)
        g_scores[warp] = s * 22.62741699796952f;   // float32(sqrt(512))
}

// ---------------------------------------------------------------------------
// JAX threefry2x32 (bit-exact), partitionable random_bits construction.
// ---------------------------------------------------------------------------
__device__ __forceinline__ uint32_t rotl32(uint32_t x, int d)
{ return (x << d) | (x >> (32 - d)); }

__device__ __forceinline__ void threefry2x32(uint32_t k0, uint32_t k1,
                                             uint32_t x0, uint32_t x1,
                                             uint32_t& o0, uint32_t& o1)
{
    uint32_t k2 = k0 ^ k1 ^ 0x1BD11BDAu;
    x0 += k0; x1 += k1;
    x0 += x1; x1 = rotl32(x1, 13); x1 ^= x0;
    x0 += x1; x1 = rotl32(x1, 15); x1 ^= x0;
    x0 += x1; x1 = rotl32(x1, 26); x1 ^= x0;
    x0 += x1; x1 = rotl32(x1,  6); x1 ^= x0;
    x0 += k1; x1 += k2 + 1u;
    x0 += x1; x1 = rotl32(x1, 17); x1 ^= x0;
    x0 += x1; x1 = rotl32(x1, 29); x1 ^= x0;
    x0 += x1; x1 = rotl32(x1, 16); x1 ^= x0;
    x0 += x1; x1 = rotl32(x1, 24); x1 ^= x0;
    x0 += k2; x1 += k0 + 2u;
    x0 += x1; x1 = rotl32(x1, 13); x1 ^= x0;
    x0 += x1; x1 = rotl32(x1, 15); x1 ^= x0;
    x0 += x1; x1 = rotl32(x1, 26); x1 ^= x0;
    x0 += x1; x1 = rotl32(x1,  6); x1 ^= x0;
    x0 += k0; x1 += k1 + 3u;
    x0 += x1; x1 = rotl32(x1, 17); x1 ^= x0;
    x0 += x1; x1 = rotl32(x1, 29); x1 ^= x0;
    x0 += x1; x1 = rotl32(x1, 16); x1 ^= x0;
    x0 += x1; x1 = rotl32(x1, 24); x1 ^= x0;
    x0 += k1; x1 += k2 + 4u;
    x0 += x1; x1 = rotl32(x1, 13); x1 ^= x0;
    x0 += x1; x1 = rotl32(x1, 15); x1 ^= x0;
    x0 += x1; x1 = rotl32(x1, 26); x1 ^= x0;
    x0 += x1; x1 = rotl32(x1,  6); x1 ^= x0;
    x0 += k2; x1 += k0 + 5u;
    o0 = x0; o1 = x1;
}

// ---------------------------------------------------------------------------
// Kernel 4: logit thresholds in parallel, then 8-lane serial scan.
// accept  <=>  u < sigmoid(z/10)  <=>  z > 10*logit(u)
// ---------------------------------------------------------------------------
__global__ void scan_kernel(float* __restrict__ out)
{
    __shared__ float s_sc[Mm];
    __shared__ float s_thr[Tt][8];

    int tid = threadIdx.x;   // 256 threads

    for (int i = tid; i < Mm; i += 256) { out[i] = 0.f; s_sc[i] = g_scores[i]; }

    {
        int t = tid;
        uint32_t kt0, kt1;
        threefry2x32(0u, 42u, 0u, (uint32_t)t, kt0, kt1);
#pragma unroll
        for (int n = 0; n < 8; ++n) {
            uint32_t o0, o1;
            threefry2x32(kt0, kt1, 0u, (uint32_t)n, o0, o1);
            uint32_t bits = (o0 ^ o1) >> 9;
            float u = __uint_as_float(bits | 0x3f800000u) - 1.0f;
            double du = (double)u;
            s_thr[t][n] = (float)(10.0 * log(du / (1.0 - du)));
        }
    }
    __syncthreads();

    if (tid < 8) {
        int n = tid;
        int x = 0, y = 0;
        const float* scn = s_sc + n * 1024;
        float* outn = out + n * 1024;
        for (int t = 0; t < Tt; ++t) {
            int idx0 = x * Bb + y;
            outn[idx0] = 1.0f;
            float z = scn[idx0] - scn[t * 4];
            int accept = (z > s_thr[t][n]) ? 1 : 0;
            if (y + accept >= Bb) accept = 0;
            y = (y + accept) * accept;
            x = accept ? x : (t + 1);
        }
    }
}

// ---------------------------------------------------------------------------
extern "C" void kernel_launch(void* const* d_in, const int* in_sizes, int n_in,
                              void* d_out, int out_size)
{
    (void)in_sizes; (void)n_in; (void)out_size;
    const float* outputs       = (const float*)d_in[0];   // [N,T,D]
    const float* block_outputs = (const float*)d_in[1];   // [N,T,B,D]
    const float* W             = (const float*)d_in[2];   // [V,D]
    float* out = (float*)d_out;                            // [N,T,B]

    convert_kernel<<<(A4 + W4 + 255) / 256, 256>>>(block_outputs, W);
    argmax_gemm_kernel<<<dim3(Mm / BM, NTILES), 256>>>();
    finalize_kernel<<<Mm / 8, 256>>>(block_outputs, W);
    scores_kernel<<<(Mm * 32) / 256, 256>>>(outputs, W);
    scan_kernel<<<1, 256>>>(out);
}